// round 3
// baseline (speedup 1.0000x reference)
#include <cuda_runtime.h>

// ============================================================================
// StablePolicy3phase (fused, single kernel):
//   out[b] = s @ Wsum - sum_h clamp(W_h s, -bn_h, bn_h) + 0.001*s
//   s = state - clamp(state, 0.97, 1.03)
//   W_h symmetric 3x3 from lambda^2, bn_h = 0.15*clip(b,0)/sum(clip(b,0))
// Identity: relu(t-c) - relu(-t-c) == t - clamp(t,-c,c) for c >= 0.
//
// R3: - prep fused into every block (table built in smem, Wsum in registers)
//     - 4-way h-split across lane octets -> 8192 warps (2048 blocks x 128)
//     - 2 rows/thread packed f32x2; epilogue: 2x shfl-xor combine
// ============================================================================

#define HN 256
#define TAB_STRIDE 16   // floats per h (64 B): d0d0 aa | cc d1d1 | ee d2d2 | bn0 bn1 bn2 pad

typedef unsigned long long u64;

__device__ __forceinline__ u64 pack2(float lo, float hi) {
    u64 r; asm("mov.b64 %0, {%1, %2};" : "=l"(r) : "f"(lo), "f"(hi)); return r;
}
__device__ __forceinline__ void unpack2(u64 v, float& lo, float& hi) {
    asm("mov.b64 {%0, %1}, %2;" : "=f"(lo), "=f"(hi) : "l"(v));
}
__device__ __forceinline__ u64 ffma2(u64 a, u64 b, u64 c) {
    u64 r; asm("fma.rn.f32x2 %0, %1, %2, %3;" : "=l"(r) : "l"(a), "l"(b), "l"(c)); return r;
}
__device__ __forceinline__ u64 fmul2(u64 a, u64 b) {
    u64 r; asm("mul.rn.f32x2 %0, %1, %2;" : "=l"(r) : "l"(a), "l"(b)); return r;
}
__device__ __forceinline__ u64 fadd2(u64 a, u64 b) {
    u64 r; asm("add.rn.f32x2 %0, %1, %2;" : "=l"(r) : "l"(a), "l"(b)); return r;
}

__device__ __forceinline__ float deadband(float v) {
    return v - fminf(fmaxf(v, 0.97f), 1.03f);
}

__device__ __forceinline__ float warp_sum(float v) {
#pragma unroll
    for (int m = 16; m > 0; m >>= 1) v += __shfl_xor_sync(0xFFFFFFFFu, v, m);
    return v;
}

// ----------------------------------------------------------------------------
// Fused kernel: 2048 blocks x 128 threads.
// Phase 1: build per-h table in smem (each thread handles h=tid and h=tid+128),
//          reduce sum(clip(b,0)) and Wsum across the block.
// Phase 2: 2 rows/thread f32x2 main loop, h split 4 ways across lane octets.
// ----------------------------------------------------------------------------
__global__ __launch_bounds__(128) void fused_kernel(
    const float* __restrict__ state,
    const float* __restrict__ b,
    const float* __restrict__ lam,
    float* __restrict__ out) {
    __shared__ float tab[HN * TAB_STRIDE];
    __shared__ float red[4 * 8];   // per-warp partials: bsum + 6 wsum

    const int tid  = threadIdx.x;
    const int lane = tid & 31;
    const int wid  = tid >> 5;

    // ---------------- Phase 1: table build + reductions ----------------
    float pb = 0.0f, pw0 = 0.0f, pw1 = 0.0f, pw2 = 0.0f, pw3 = 0.0f, pw4 = 0.0f, pw5 = 0.0f;
#pragma unroll
    for (int r = 0; r < 2; r++) {
        int h = tid + r * 128;
        float l2[6];
#pragma unroll
        for (int k = 0; k < 6; k++) { float v = lam[h * 6 + k]; l2[k] = v * v; }
        // basis order: (0,0),(1,0),(1,1),(2,0),(2,1),(2,2)
        float d0 = l2[0] + l2[1] + l2[3];   // W00
        float d1 = l2[1] + l2[2] + l2[4];   // W11
        float d2 = l2[3] + l2[4] + l2[5];   // W22
        float a  = -l2[1];                  // W01
        float c  = -l2[3];                  // W02
        float e  = -l2[4];                  // W12

        float b0 = fmaxf(b[h * 3 + 0], 0.0f);
        float b1 = fmaxf(b[h * 3 + 1], 0.0f);
        float b2 = fmaxf(b[h * 3 + 2], 0.0f);

        pb += b0 + b1 + b2;
        pw0 += d0; pw1 += a; pw2 += c; pw3 += d1; pw4 += e; pw5 += d2;

        float* t = tab + h * TAB_STRIDE;
        t[0]  = d0;  t[1]  = d0;
        t[2]  = a;   t[3]  = a;
        t[4]  = c;   t[5]  = c;
        t[6]  = d1;  t[7]  = d1;
        t[8]  = e;   t[9]  = e;
        t[10] = d2;  t[11] = d2;
        t[12] = b0;  t[13] = b1;  t[14] = b2;  t[15] = 0.0f;   // raw; scaled below
    }

    // warp-level butterfly reduce (all lanes get the warp total)
    pb  = warp_sum(pb);
    pw0 = warp_sum(pw0); pw1 = warp_sum(pw1); pw2 = warp_sum(pw2);
    pw3 = warp_sum(pw3); pw4 = warp_sum(pw4); pw5 = warp_sum(pw5);
    if (lane == 0) {
        float* rr = red + wid * 8;
        rr[0] = pb; rr[1] = pw0; rr[2] = pw1; rr[3] = pw2;
        rr[4] = pw3; rr[5] = pw4; rr[6] = pw5;
    }
    __syncthreads();

    float bsum = red[0] + red[8] + red[16] + red[24];
    float ws00 = red[1] + red[9]  + red[17] + red[25];
    float ws01 = red[2] + red[10] + red[18] + red[26];
    float ws02 = red[3] + red[11] + red[19] + red[27];
    float ws11 = red[4] + red[12] + red[20] + red[28];
    float ws12 = red[5] + red[13] + red[21] + red[29];
    float ws22 = red[6] + red[14] + red[22] + red[30];

    float inv = 0.15f / bsum;
#pragma unroll
    for (int r = 0; r < 2; r++) {
        float* t = tab + (tid + r * 128) * TAB_STRIDE;
        t[12] *= inv; t[13] *= inv; t[14] *= inv;
    }
    __syncthreads();

    // ---------------- Phase 2: main loop ----------------
    const int warpGlobal = blockIdx.x * 4 + wid;
    const int g = warpGlobal * 8 + (lane & 7);   // row-pair id: rows 2g, 2g+1
    const int quarter = lane >> 3;               // h range: [quarter*64, +64)

    const float2* st = (const float2*)state + (size_t)g * 3;
    float2 v01  = st[0];
    float2 v2_0 = st[1];
    float2 v12  = st[2];

    float sa0 = deadband(v01.x),  sa1 = deadband(v01.y),  sa2 = deadband(v2_0.x);
    float sb0 = deadband(v2_0.y), sb1 = deadband(v12.x),  sb2 = deadband(v12.y);

    u64 S0 = pack2(sa0, sb0);
    u64 S1 = pack2(sa1, sb1);
    u64 S2 = pack2(sa2, sb2);

    u64 acc0 = 0ull, acc1 = 0ull, acc2 = 0ull;

    const float* tb = tab + quarter * (HN / 4) * TAB_STRIDE;

#pragma unroll 8
    for (int h = 0; h < HN / 4; h++) {
        const ulonglong2* tp = (const ulonglong2*)(tb + h * TAB_STRIDE);
        ulonglong2 p0 = tp[0];   // D0 | A    (each u64 = duplicated f32 pair)
        ulonglong2 p1 = tp[1];   // C  | D1
        ulonglong2 p2 = tp[2];   // E  | D2
        float4 q3 = ((const float4*)tp)[3];   // bn0 bn1 bn2 pad

        u64 sw0 = ffma2(p1.x, S2, ffma2(p0.y, S1, fmul2(p0.x, S0)));
        u64 sw1 = ffma2(p2.x, S2, ffma2(p1.y, S1, fmul2(p0.y, S0)));
        u64 sw2 = ffma2(p2.y, S2, ffma2(p2.x, S1, fmul2(p1.x, S0)));

        float w0a, w0b, w1a, w1b, w2a, w2b;
        unpack2(sw0, w0a, w0b);
        unpack2(sw1, w1a, w1b);
        unpack2(sw2, w2a, w2b);

        float t0a = fminf(fmaxf(w0a, -q3.x), q3.x);
        float t0b = fminf(fmaxf(w0b, -q3.x), q3.x);
        float t1a = fminf(fmaxf(w1a, -q3.y), q3.y);
        float t1b = fminf(fmaxf(w1b, -q3.y), q3.y);
        float t2a = fminf(fmaxf(w2a, -q3.z), q3.z);
        float t2b = fminf(fmaxf(w2b, -q3.z), q3.z);

        acc0 = fadd2(acc0, pack2(t0a, t0b));
        acc1 = fadd2(acc1, pack2(t1a, t1b));
        acc2 = fadd2(acc2, pack2(t2a, t2b));
    }

    // combine the 4 h-quarters (lanes sharing (lane & 7) hold the same pair)
    acc0 = fadd2(acc0, __shfl_xor_sync(0xFFFFFFFFu, acc0, 8));
    acc1 = fadd2(acc1, __shfl_xor_sync(0xFFFFFFFFu, acc1, 8));
    acc2 = fadd2(acc2, __shfl_xor_sync(0xFFFFFFFFu, acc2, 8));
    acc0 = fadd2(acc0, __shfl_xor_sync(0xFFFFFFFFu, acc0, 16));
    acc1 = fadd2(acc1, __shfl_xor_sync(0xFFFFFFFFu, acc1, 16));
    acc2 = fadd2(acc2, __shfl_xor_sync(0xFFFFFFFFu, acc2, 16));

    if (quarter == 0) {
        float a0, a0b, a1, a1b, a2, a2b;
        unpack2(acc0, a0, a0b);
        unpack2(acc1, a1, a1b);
        unpack2(acc2, a2, a2b);

        float la0 = ws00 * sa0 + ws01 * sa1 + ws02 * sa2;
        float la1 = ws01 * sa0 + ws11 * sa1 + ws12 * sa2;
        float la2 = ws02 * sa0 + ws12 * sa1 + ws22 * sa2;
        float lb0 = ws00 * sb0 + ws01 * sb1 + ws02 * sb2;
        float lb1 = ws01 * sb0 + ws11 * sb1 + ws12 * sb2;
        float lb2 = ws02 * sb0 + ws12 * sb1 + ws22 * sb2;

        float oA0 = la0 - a0  + 0.001f * sa0;
        float oA1 = la1 - a1  + 0.001f * sa1;
        float oA2 = la2 - a2  + 0.001f * sa2;
        float oB0 = lb0 - a0b + 0.001f * sb0;
        float oB1 = lb1 - a1b + 0.001f * sb1;
        float oB2 = lb2 - a2b + 0.001f * sb2;

        float2* op = (float2*)out + (size_t)g * 3;
        op[0] = make_float2(oA0, oA1);
        op[1] = make_float2(oA2, oB0);
        op[2] = make_float2(oB1, oB2);
    }
}

extern "C" void kernel_launch(void* const* d_in, const int* in_sizes, int n_in,
                              void* d_out, int out_size) {
    const float* state = (const float*)d_in[0];   // [131072, 3]
    const float* b     = (const float*)d_in[1];   // [256, 3]
    const float* lam   = (const float*)d_in[2];   // [256, 6]
    float* out = (float*)d_out;                   // [131072, 3]

    // 65536 row-pairs, 8 pairs per warp (x4 h-quarters), 4 warps per block
    fused_kernel<<<2048, 128>>>(state, b, lam, out);
}

// round 4
// speedup vs baseline: 1.4509x; 1.4509x over previous
#include <cuda_runtime.h>

// ============================================================================
// StablePolicy3phase (fused, single kernel):
//   out[b] = s @ Wsum - sum_h clamp(W_h s, -bn_h, bn_h) + 0.001*s
//   s = state - clamp(state, 0.97, 1.03)
//   W_h symmetric 3x3 from lambda^2, bn_h = 0.15*clip(b,0)/sum(clip(b,0))
// Identity: relu(t-c) - relu(-t-c) == t - clamp(t,-c,c) for c >= 0.
//
// R4: - per-quarter table skew (+16B) -> conflict-free LDS across lane groups
//     - 2 row-pairs (4 rows) per thread: halves LDS per pair, 2x ILP
//     - 4-way h-split across lane octets; 4096 warps (1024 blocks x 128)
// ============================================================================

#define HN 256
#define TAB_STRIDE 16                 // floats per h (64 B)
#define QH (HN / 4)                   // 64 h per quarter
#define Q_STRIDE (QH * TAB_STRIDE + 4)  // 1028 floats = 4112 B (skew: +16B per quarter)

typedef unsigned long long u64;

__device__ __forceinline__ u64 pack2(float lo, float hi) {
    u64 r; asm("mov.b64 %0, {%1, %2};" : "=l"(r) : "f"(lo), "f"(hi)); return r;
}
__device__ __forceinline__ void unpack2(u64 v, float& lo, float& hi) {
    asm("mov.b64 {%0, %1}, %2;" : "=f"(lo), "=f"(hi) : "l"(v));
}
__device__ __forceinline__ u64 ffma2(u64 a, u64 b, u64 c) {
    u64 r; asm("fma.rn.f32x2 %0, %1, %2, %3;" : "=l"(r) : "l"(a), "l"(b), "l"(c)); return r;
}
__device__ __forceinline__ u64 fmul2(u64 a, u64 b) {
    u64 r; asm("mul.rn.f32x2 %0, %1, %2;" : "=l"(r) : "l"(a), "l"(b)); return r;
}
__device__ __forceinline__ u64 fadd2(u64 a, u64 b) {
    u64 r; asm("add.rn.f32x2 %0, %1, %2;" : "=l"(r) : "l"(a), "l"(b)); return r;
}

__device__ __forceinline__ float deadband(float v) {
    return v - fminf(fmaxf(v, 0.97f), 1.03f);
}

__device__ __forceinline__ float warp_sum(float v) {
#pragma unroll
    for (int m = 16; m > 0; m >>= 1) v += __shfl_xor_sync(0xFFFFFFFFu, v, m);
    return v;
}

// ----------------------------------------------------------------------------
// Fused kernel: 1024 blocks x 128 threads.
// Phase 1: build skewed per-h table in smem; block-reduce sum(clip(b,0)), Wsum.
// Phase 2: 2 pairs/thread f32x2 main loop, h split 4 ways across lane octets.
// ----------------------------------------------------------------------------
__global__ __launch_bounds__(128) void fused_kernel(
    const float* __restrict__ state,
    const float* __restrict__ b,
    const float* __restrict__ lam,
    float* __restrict__ out) {
    __shared__ float tab[4 * Q_STRIDE];
    __shared__ float red[4 * 8];

    const int tid  = threadIdx.x;
    const int lane = tid & 31;
    const int wid  = tid >> 5;

    // ---------------- Phase 1: table build + reductions ----------------
    float pb = 0.0f, pw0 = 0.0f, pw1 = 0.0f, pw2 = 0.0f, pw3 = 0.0f, pw4 = 0.0f, pw5 = 0.0f;
#pragma unroll
    for (int r = 0; r < 2; r++) {
        int h = tid + r * 128;
        float l2[6];
#pragma unroll
        for (int k = 0; k < 6; k++) { float v = lam[h * 6 + k]; l2[k] = v * v; }
        // basis order: (0,0),(1,0),(1,1),(2,0),(2,1),(2,2)
        float d0 = l2[0] + l2[1] + l2[3];   // W00
        float d1 = l2[1] + l2[2] + l2[4];   // W11
        float d2 = l2[3] + l2[4] + l2[5];   // W22
        float a  = -l2[1];                  // W01
        float c  = -l2[3];                  // W02
        float e  = -l2[4];                  // W12

        float b0 = fmaxf(b[h * 3 + 0], 0.0f);
        float b1 = fmaxf(b[h * 3 + 1], 0.0f);
        float b2 = fmaxf(b[h * 3 + 2], 0.0f);

        pb += b0 + b1 + b2;
        pw0 += d0; pw1 += a; pw2 += c; pw3 += d1; pw4 += e; pw5 += d2;

        float* t = tab + (h >> 6) * Q_STRIDE + (h & (QH - 1)) * TAB_STRIDE;
        t[0]  = d0;  t[1]  = d0;
        t[2]  = a;   t[3]  = a;
        t[4]  = c;   t[5]  = c;
        t[6]  = d1;  t[7]  = d1;
        t[8]  = e;   t[9]  = e;
        t[10] = d2;  t[11] = d2;
        t[12] = b0;  t[13] = b1;  t[14] = b2;  t[15] = 0.0f;   // raw; scaled below
    }

    pb  = warp_sum(pb);
    pw0 = warp_sum(pw0); pw1 = warp_sum(pw1); pw2 = warp_sum(pw2);
    pw3 = warp_sum(pw3); pw4 = warp_sum(pw4); pw5 = warp_sum(pw5);
    if (lane == 0) {
        float* rr = red + wid * 8;
        rr[0] = pb; rr[1] = pw0; rr[2] = pw1; rr[3] = pw2;
        rr[4] = pw3; rr[5] = pw4; rr[6] = pw5;
    }
    __syncthreads();

    float bsum = red[0] + red[8] + red[16] + red[24];
    float ws00 = red[1] + red[9]  + red[17] + red[25];
    float ws01 = red[2] + red[10] + red[18] + red[26];
    float ws02 = red[3] + red[11] + red[19] + red[27];
    float ws11 = red[4] + red[12] + red[20] + red[28];
    float ws12 = red[5] + red[13] + red[21] + red[29];
    float ws22 = red[6] + red[14] + red[22] + red[30];

    float inv = 0.15f / bsum;
#pragma unroll
    for (int r = 0; r < 2; r++) {
        int h = tid + r * 128;
        float* t = tab + (h >> 6) * Q_STRIDE + (h & (QH - 1)) * TAB_STRIDE;
        t[12] *= inv; t[13] *= inv; t[14] *= inv;
    }
    __syncthreads();

    // ---------------- Phase 2: main loop ----------------
    const int warpGlobal = blockIdx.x * 4 + wid;
    const int octet   = lane & 7;
    const int quarter = lane >> 3;                  // h range: [quarter*64, +64)
    const int gA = warpGlobal * 16 + octet;         // pair A (rows 2gA, 2gA+1)
    const int gB = gA + 8;                          // pair B

    const float2* stA = (const float2*)state + (size_t)gA * 3;
    const float2* stB = (const float2*)state + (size_t)gB * 3;
    float2 a01 = stA[0], a20 = stA[1], a12 = stA[2];
    float2 b01 = stB[0], b20 = stB[1], b12 = stB[2];

    float sa0 = deadband(a01.x), sa1 = deadband(a01.y), sa2 = deadband(a20.x);
    float sa3 = deadband(a20.y), sa4 = deadband(a12.x), sa5 = deadband(a12.y);
    float sb0 = deadband(b01.x), sb1 = deadband(b01.y), sb2 = deadband(b20.x);
    float sb3 = deadband(b20.y), sb4 = deadband(b12.x), sb5 = deadband(b12.y);

    // pair A = rows (2gA, 2gA+1): components packed (rowLo, rowHi)
    u64 SA0 = pack2(sa0, sa3), SA1 = pack2(sa1, sa4), SA2 = pack2(sa2, sa5);
    u64 SB0 = pack2(sb0, sb3), SB1 = pack2(sb1, sb4), SB2 = pack2(sb2, sb5);

    u64 accA0 = 0ull, accA1 = 0ull, accA2 = 0ull;
    u64 accB0 = 0ull, accB1 = 0ull, accB2 = 0ull;

    const float* tb = tab + quarter * Q_STRIDE;

#pragma unroll 4
    for (int h = 0; h < QH; h++) {
        const ulonglong2* tp = (const ulonglong2*)(tb + h * TAB_STRIDE);
        ulonglong2 p0 = tp[0];   // D0 | A
        ulonglong2 p1 = tp[1];   // C  | D1
        ulonglong2 p2 = tp[2];   // E  | D2
        float4 q3 = ((const float4*)tp)[3];   // bn0 bn1 bn2 pad

        u64 swA0 = ffma2(p1.x, SA2, ffma2(p0.y, SA1, fmul2(p0.x, SA0)));
        u64 swA1 = ffma2(p2.x, SA2, ffma2(p1.y, SA1, fmul2(p0.y, SA0)));
        u64 swA2 = ffma2(p2.y, SA2, ffma2(p2.x, SA1, fmul2(p1.x, SA0)));
        u64 swB0 = ffma2(p1.x, SB2, ffma2(p0.y, SB1, fmul2(p0.x, SB0)));
        u64 swB1 = ffma2(p2.x, SB2, ffma2(p1.y, SB1, fmul2(p0.y, SB0)));
        u64 swB2 = ffma2(p2.y, SB2, ffma2(p2.x, SB1, fmul2(p1.x, SB0)));

        float wA0l, wA0h, wA1l, wA1h, wA2l, wA2h;
        float wB0l, wB0h, wB1l, wB1h, wB2l, wB2h;
        unpack2(swA0, wA0l, wA0h);
        unpack2(swA1, wA1l, wA1h);
        unpack2(swA2, wA2l, wA2h);
        unpack2(swB0, wB0l, wB0h);
        unpack2(swB1, wB1l, wB1h);
        unpack2(swB2, wB2l, wB2h);

        // clamp(sw, -bn, bn): FMNMX, negate folded into source modifier
        float tA0l = fminf(fmaxf(wA0l, -q3.x), q3.x);
        float tA0h = fminf(fmaxf(wA0h, -q3.x), q3.x);
        float tA1l = fminf(fmaxf(wA1l, -q3.y), q3.y);
        float tA1h = fminf(fmaxf(wA1h, -q3.y), q3.y);
        float tA2l = fminf(fmaxf(wA2l, -q3.z), q3.z);
        float tA2h = fminf(fmaxf(wA2h, -q3.z), q3.z);
        float tB0l = fminf(fmaxf(wB0l, -q3.x), q3.x);
        float tB0h = fminf(fmaxf(wB0h, -q3.x), q3.x);
        float tB1l = fminf(fmaxf(wB1l, -q3.y), q3.y);
        float tB1h = fminf(fmaxf(wB1h, -q3.y), q3.y);
        float tB2l = fminf(fmaxf(wB2l, -q3.z), q3.z);
        float tB2h = fminf(fmaxf(wB2h, -q3.z), q3.z);

        accA0 = fadd2(accA0, pack2(tA0l, tA0h));
        accA1 = fadd2(accA1, pack2(tA1l, tA1h));
        accA2 = fadd2(accA2, pack2(tA2l, tA2h));
        accB0 = fadd2(accB0, pack2(tB0l, tB0h));
        accB1 = fadd2(accB1, pack2(tB1l, tB1h));
        accB2 = fadd2(accB2, pack2(tB2l, tB2h));
    }

    // combine the 4 h-quarters (lanes sharing (lane & 7) hold the same pairs)
#pragma unroll
    for (int m = 8; m <= 16; m <<= 1) {
        accA0 = fadd2(accA0, __shfl_xor_sync(0xFFFFFFFFu, accA0, m));
        accA1 = fadd2(accA1, __shfl_xor_sync(0xFFFFFFFFu, accA1, m));
        accA2 = fadd2(accA2, __shfl_xor_sync(0xFFFFFFFFu, accA2, m));
        accB0 = fadd2(accB0, __shfl_xor_sync(0xFFFFFFFFu, accB0, m));
        accB1 = fadd2(accB1, __shfl_xor_sync(0xFFFFFFFFu, accB1, m));
        accB2 = fadd2(accB2, __shfl_xor_sync(0xFFFFFFFFu, accB2, m));
    }

    if (quarter == 0) {
        float A0l, A0h, A1l, A1h, A2l, A2h;
        float B0l, B0h, B1l, B1h, B2l, B2h;
        unpack2(accA0, A0l, A0h);
        unpack2(accA1, A1l, A1h);
        unpack2(accA2, A2l, A2h);
        unpack2(accB0, B0l, B0h);
        unpack2(accB1, B1l, B1h);
        unpack2(accB2, B2l, B2h);

        // pair A rows
        float lA0 = ws00 * sa0 + ws01 * sa1 + ws02 * sa2;
        float lA1 = ws01 * sa0 + ws11 * sa1 + ws12 * sa2;
        float lA2 = ws02 * sa0 + ws12 * sa1 + ws22 * sa2;
        float lA3 = ws00 * sa3 + ws01 * sa4 + ws02 * sa5;
        float lA4 = ws01 * sa3 + ws11 * sa4 + ws12 * sa5;
        float lA5 = ws02 * sa3 + ws12 * sa4 + ws22 * sa5;
        // pair B rows
        float lB0 = ws00 * sb0 + ws01 * sb1 + ws02 * sb2;
        float lB1 = ws01 * sb0 + ws11 * sb1 + ws12 * sb2;
        float lB2 = ws02 * sb0 + ws12 * sb1 + ws22 * sb2;
        float lB3 = ws00 * sb3 + ws01 * sb4 + ws02 * sb5;
        float lB4 = ws01 * sb3 + ws11 * sb4 + ws12 * sb5;
        float lB5 = ws02 * sb3 + ws12 * sb4 + ws22 * sb5;

        float2* opA = (float2*)out + (size_t)gA * 3;
        opA[0] = make_float2(lA0 - A0l + 0.001f * sa0, lA1 - A1l + 0.001f * sa1);
        opA[1] = make_float2(lA2 - A2l + 0.001f * sa2, lA3 - A0h + 0.001f * sa3);
        opA[2] = make_float2(lA4 - A1h + 0.001f * sa4, lA5 - A2h + 0.001f * sa5);

        float2* opB = (float2*)out + (size_t)gB * 3;
        opB[0] = make_float2(lB0 - B0l + 0.001f * sb0, lB1 - B1l + 0.001f * sb1);
        opB[1] = make_float2(lB2 - B2l + 0.001f * sb2, lB3 - B0h + 0.001f * sb3);
        opB[2] = make_float2(lB4 - B1h + 0.001f * sb4, lB5 - B2h + 0.001f * sb5);
    }
}

extern "C" void kernel_launch(void* const* d_in, const int* in_sizes, int n_in,
                              void* d_out, int out_size) {
    const float* state = (const float*)d_in[0];   // [131072, 3]
    const float* b     = (const float*)d_in[1];   // [256, 3]
    const float* lam   = (const float*)d_in[2];   // [256, 6]
    float* out = (float*)d_out;                   // [131072, 3]

    // 65536 row-pairs, 16 pairs per warp (2 per thread x 8 octet lanes,
    // x4 h-quarters), 4 warps per block
    fused_kernel<<<1024, 128>>>(state, b, lam, out);
}